// round 7
// baseline (speedup 1.0000x reference)
#include <cuda_runtime.h>
#include <cuda_bf16.h>

// Reference output is identically zero (the reference's pad/slice selects the
// zero-pad slice of a size-1 dim and discards all data — verified symbolically
// in R1; rel_err=0 in R2,R3,R4,R6). Required work = write 411MB of zeros.
//
// Measured plateau: R2/R3/R6 all ~55.3-55.8us kernel @ 6.3 TB/s DRAM-write,
// DRAM=79-80%, issue<10% — at the store-stream roofline. This round tests the
// one untried path: the driver's memset fill kernel via cudaMemsetAsync
// (graph-capturable memset node, vendor-tuned store forms).

// Proven fallback: predicate-free exact-cover float4 fill (R6, 55.78us).
__global__ void __launch_bounds__(256) zero_fill_exact(float4* __restrict__ out) {
    const float4 z = make_float4(0.f, 0.f, 0.f, 0.f);
    float4* p = out + (long long)blockIdx.x * 1024 + threadIdx.x;
#pragma unroll
    for (int j = 0; j < 4; j++) {
        __stcs(p + j * 256, z);
    }
}

__global__ void __launch_bounds__(256) zero_fill_guarded(float4* __restrict__ out,
                                                         long long n4) {
    const float4 z = make_float4(0.f, 0.f, 0.f, 0.f);
    long long base = (long long)blockIdx.x * 1024 + threadIdx.x;
#pragma unroll
    for (int j = 0; j < 4; j++) {
        long long idx = base + (long long)j * 256;
        if (idx < n4) __stcs(out + idx, z);
    }
}

__global__ void zero_fill_tail(float* __restrict__ out,
                               long long start, long long n_total) {
    long long i = start + (long long)blockIdx.x * blockDim.x + threadIdx.x;
    if (i < n_total) out[i] = 0.f;
}

extern "C" void kernel_launch(void* const* d_in, const int* in_sizes, int n_in,
                              void* d_out, int out_size) {
    (void)d_in; (void)in_sizes; (void)n_in;

    long long n_total = (long long)out_size;        // 102,760,448 expected
    size_t bytes = (size_t)n_total * sizeof(float); // 411,041,792 bytes

    // Vendor fill path: single capturable memset node, no alloc, async.
    cudaError_t err = cudaMemsetAsync(d_out, 0, bytes, 0);

    if (err != cudaSuccess) {
        // Fallback to our proven STG.128 fill (never expected to trigger).
        long long n4 = n_total / 4;
        const int threads = 256;
        if (n_total % 4096 == 0) {
            zero_fill_exact<<<(unsigned)(n4 >> 10), threads>>>((float4*)d_out);
        } else {
            long long blocks = (n4 + 1023) >> 10;
            if (blocks > 0)
                zero_fill_guarded<<<(unsigned)blocks, threads>>>((float4*)d_out, n4);
            long long tail = n_total - n4 * 4;
            if (tail > 0)
                zero_fill_tail<<<1, 256>>>((float*)d_out, n4 * 4, n_total);
        }
    }
}

// round 8
// speedup vs baseline: 1.0164x; 1.0164x over previous
#include <cuda_runtime.h>
#include <cuda_bf16.h>

// FINAL — frozen at the measured roofline.
//
// Reference output is identically zero: with factor=2, the reference's pad
// spec pads the SIZE-1 dim1 of y.reshape(-1,1,Hf,Wf) by (1,0) and the
// subsequent slice [:, 0:1] selects the zero-pad slice, discarding all data;
// the conv/resize of zeros stays zero (verified symbolically R1; rel_err=0
// in every passing bench R2,R3,R4,R6,R7).
//
// Required work: write 102,760,448 float zeros (411 MB).
// Measured plateau across R2/R3/R6/R7 (scalar/vec4/predicated/stcs/memset):
// 55.3-55.8us kernel = 6.3-6.35 TB/s DRAM write, DRAM~80%, issue<10%.
// That is the B300 store-stream roofline; persistent CTAs (R4) regress.
//
// Best shape: 25,088 fire-and-exit CTAs x 256 threads, 4 coalesced
// float4 (STG.E.128) stores per thread, exact cover, predicate-free.

__global__ void __launch_bounds__(256) zero_fill_exact(float4* __restrict__ out) {
    const float4 z = make_float4(0.f, 0.f, 0.f, 0.f);
    float4* p = out + (long long)blockIdx.x * 1024 + threadIdx.x;
#pragma unroll
    for (int j = 0; j < 4; j++) {
        p[j * 256] = z;
    }
}

// Generic path for any other size (never taken for this problem's shape).
__global__ void __launch_bounds__(256) zero_fill_guarded(float4* __restrict__ out,
                                                         long long n4) {
    const float4 z = make_float4(0.f, 0.f, 0.f, 0.f);
    long long base = (long long)blockIdx.x * 1024 + threadIdx.x;
#pragma unroll
    for (int j = 0; j < 4; j++) {
        long long idx = base + (long long)j * 256;
        if (idx < n4) out[idx] = z;
    }
}

__global__ void zero_fill_tail(float* __restrict__ out,
                               long long start, long long n_total) {
    long long i = start + (long long)blockIdx.x * blockDim.x + threadIdx.x;
    if (i < n_total) out[i] = 0.f;
}

extern "C" void kernel_launch(void* const* d_in, const int* in_sizes, int n_in,
                              void* d_out, int out_size) {
    (void)d_in; (void)in_sizes; (void)n_in;

    long long n_total = (long long)out_size;   // 102,760,448 expected
    long long n4 = n_total / 4;                // 25,690,112 float4s
    const int threads = 256;

    if (n_total % 4096 == 0) {
        // 1024 float4s per block; exact cover, no predicates, no tail.
        zero_fill_exact<<<(unsigned)(n4 >> 10), threads>>>((float4*)d_out);
    } else {
        long long blocks = (n4 + 1023) >> 10;
        if (blocks > 0)
            zero_fill_guarded<<<(unsigned)blocks, threads>>>((float4*)d_out, n4);
        long long tail = n_total - n4 * 4;
        if (tail > 0)
            zero_fill_tail<<<1, 256>>>((float*)d_out, n4 * 4, n_total);
    }
}

// round 9
// speedup vs baseline: 1.0209x; 1.0044x over previous
#include <cuda_runtime.h>
#include <cuda_bf16.h>

// FINAL — frozen at the measured DRAM-write roofline (R3 configuration,
// the best single measurement: 55.30us kernel, DRAM=80.1%, 6.35 TB/s).
//
// Reference output is identically zero: with factor=2, the reference pads the
// SIZE-1 dim1 of y.reshape(-1,1,Hf,Wf) by (1,0) and the subsequent slice
// [:, 0:1] selects the zero-pad slice, discarding all data; conv/resize of
// zeros stays zero (symbolic proof R1; rel_err=0 in R2,R3,R4,R6,R7,R8).
//
// Required work: write 102,760,448 float zeros (411 MB).
// Plateau evidence (kernel time / DRAM%):
//   R2 1xf4/thread           55.68 / 79.4
//   R3 4xf4/thread guarded   55.30 / 80.1   <- best, this file
//   R4 persistent CTAs       66.82 / 66.1   (regression: store-MLP starved)
//   R6 predicate-free +stcs  55.78 / 79.5
//   R7 cudaMemsetAsync       ~57   /  --
//   R8 predicate-free        56.06 / 79.1
// All well-formed store streams land at 6.3-6.35 TB/s — the hardware floor.

__global__ void __launch_bounds__(256) zero_fill_v4x4(float4* __restrict__ out,
                                                      long long n4) {
    const float4 z = make_float4(0.f, 0.f, 0.f, 0.f);
    // Block tile: 1024 float4s (16 KB); each warp issues 4 coalesced 512B
    // store bursts. 25,088 fire-and-exit CTAs keep the store queues saturated.
    long long base = (long long)blockIdx.x * 1024 + threadIdx.x;
#pragma unroll
    for (int j = 0; j < 4; j++) {
        long long idx = base + (long long)j * 256;
        if (idx < n4) out[idx] = z;
    }
}

// Scalar tail for out_size % 4 != 0 (dead for this shape; kept for generality).
__global__ void zero_fill_tail(float* __restrict__ out,
                               long long start, long long n_total) {
    long long i = start + (long long)blockIdx.x * blockDim.x + threadIdx.x;
    if (i < n_total) out[i] = 0.f;
}

extern "C" void kernel_launch(void* const* d_in, const int* in_sizes, int n_in,
                              void* d_out, int out_size) {
    (void)d_in; (void)in_sizes; (void)n_in;

    long long n_total = (long long)out_size;   // 102,760,448 expected
    long long n4 = n_total / 4;                // 25,690,112 float4s

    const int threads = 256;
    long long blocks = (n4 + 1023) / 1024;     // 25,088 blocks expected

    if (blocks > 0) {
        zero_fill_v4x4<<<(unsigned)blocks, threads>>>((float4*)d_out, n4);
    }

    long long tail = n_total - n4 * 4;         // 0 for this shape
    if (tail > 0) {
        zero_fill_tail<<<1, 256>>>((float*)d_out, n4 * 4, n_total);
    }
}

// round 10
// speedup vs baseline: 1.0260x; 1.0050x over previous
#include <cuda_runtime.h>
#include <cuda_bf16.h>

// Reference output is identically zero: with factor=2, the reference pads the
// SIZE-1 dim1 of y.reshape(-1,1,Hf,Wf) by (1,0) and the subsequent slice
// [:, 0:1] selects the zero-pad slice, discarding all data (symbolic proof R1;
// rel_err=0 in all passing rounds). Work = write 102,760,448 float zeros.
//
// Plateau: all store-stream variants land 55.3-56.1us @ ~6.3 TB/s DRAM write.
// This round probes the last point on the granularity axis: 8 float4s/thread
// (32KB tile, 12,544 fire-and-exit CTAs) — midpoint between R3's 25K-block
// optimum and R4's failed persistent form.

__global__ void __launch_bounds__(256) zero_fill_v4x8(float4* __restrict__ out,
                                                      long long n4) {
    const float4 z = make_float4(0.f, 0.f, 0.f, 0.f);
    // Block tile: 2048 float4s (32 KB); 8 coalesced 512B bursts per warp.
    long long base = (long long)blockIdx.x * 2048 + threadIdx.x;
#pragma unroll
    for (int j = 0; j < 8; j++) {
        long long idx = base + (long long)j * 256;
        if (idx < n4) out[idx] = z;
    }
}

// Scalar tail for out_size % 4 != 0 (dead for this shape; kept for generality).
__global__ void zero_fill_tail(float* __restrict__ out,
                               long long start, long long n_total) {
    long long i = start + (long long)blockIdx.x * blockDim.x + threadIdx.x;
    if (i < n_total) out[i] = 0.f;
}

extern "C" void kernel_launch(void* const* d_in, const int* in_sizes, int n_in,
                              void* d_out, int out_size) {
    (void)d_in; (void)in_sizes; (void)n_in;

    long long n_total = (long long)out_size;   // 102,760,448 expected
    long long n4 = n_total / 4;                // 25,690,112 float4s

    const int threads = 256;
    long long blocks = (n4 + 2047) / 2048;     // 12,544 blocks expected

    if (blocks > 0) {
        zero_fill_v4x8<<<(unsigned)blocks, threads>>>((float4*)d_out, n4);
    }

    long long tail = n_total - n4 * 4;         // 0 for this shape
    if (tail > 0) {
        zero_fill_tail<<<1, 256>>>((float*)d_out, n4 * 4, n_total);
    }
}